// round 13
// baseline (speedup 1.0000x reference)
#include <cuda_runtime.h>
#include <cuda_bf16.h>
#include <cstdint>

// Dims: B=4, C_IN=64, C_OUT=128, H=W=256, HO=WO=128, K=3 (9 taps), K_OFF=7

// ---------------- scratch ----------------
__device__ float g_offp[4 * 18 * 128 * 128];       // offset conv output
__device__ float g_wtA[8 * 128 * 76];              // deform A: [group8ch][m][76]
__device__ float g_wtB[64 * 7 * 8 * 24];           // offset weights: [ch][ky][kx8][oc24]
__device__ float g_psum[512 * 16];
__device__ float g_psq[512 * 16];

// ---------------- helpers ----------------
__device__ __forceinline__ uint32_t smem_u32(const void* p) {
    uint32_t a;
    asm("{ .reg .u64 t; cvta.to.shared.u64 t, %1; cvt.u32.u64 %0, t; }" : "=r"(a) : "l"(p));
    return a;
}
__device__ __forceinline__ uint32_t f2tf32(float f) {
    uint32_t u;
    asm("cvt.rna.tf32.f32 %0, %1;" : "=r"(u) : "f"(f));
    return u;
}
__device__ __forceinline__ void mma_tf32(float* d, uint32_t a0, uint32_t a1,
                                         uint32_t a2, uint32_t a3,
                                         uint32_t b0, uint32_t b1) {
    asm volatile(
        "mma.sync.aligned.m16n8k8.row.col.f32.tf32.tf32.f32 "
        "{%0,%1,%2,%3}, {%4,%5,%6,%7}, {%8,%9}, {%0,%1,%2,%3};"
        : "+f"(d[0]), "+f"(d[1]), "+f"(d[2]), "+f"(d[3])
        : "r"(a0), "r"(a1), "r"(a2), "r"(a3), "r"(b0), "r"(b1));
}
__device__ __forceinline__ void ldsm_x4(uint32_t& r0, uint32_t& r1, uint32_t& r2,
                                        uint32_t& r3, uint32_t addr) {
    asm volatile("ldmatrix.sync.aligned.m8n8.x4.shared.b16 {%0,%1,%2,%3}, [%4];"
                 : "=r"(r0), "=r"(r1), "=r"(r2), "=r"(r3) : "r"(addr));
}

#define CPA16(dst, src, sz) \
    asm volatile("cp.async.cg.shared.global [%0], [%1], 16, %2;" :: "r"(dst), "l"(src), "r"(sz))
#define CPA_COMMIT() asm volatile("cp.async.commit_group;" ::: "memory")
#define CPA_WAIT0()  asm volatile("cp.async.wait_group 0;" ::: "memory")

// ---------------------------------------------------------------------------
// Kernel 0a: deform-conv A prep
// ---------------------------------------------------------------------------
__global__ __launch_bounds__(256) void prep_wt_kernel(const float* __restrict__ weight)
{
    int idx = blockIdx.x * 256 + threadIdx.x;       // 77824 total
    if (idx >= 8 * 128 * 76) return;
    int g   = idx / 9728;
    int rem = idx - g * 9728;
    int m   = rem / 76;
    int kk  = rem - m * 76;
    float v = (kk < 72) ? weight[m * 576 + g * 72 + kk] : 0.f;
    g_wtA[idx] = __uint_as_float(f2tf32(v));
}

// ---------------------------------------------------------------------------
// Kernel 0b: offset-conv weight prep: g_wtB[c][ky][kx(8)][oc(24)]
// ---------------------------------------------------------------------------
__global__ __launch_bounds__(256) void prep_wtB_kernel(const float* __restrict__ w_off)
{
    int idx = blockIdx.x * 256 + threadIdx.x;
    if (idx >= 64 * 1344) return;
    int c  = idx / 1344;
    int r  = idx - c * 1344;
    int ky = r / 192;
    int r2 = r - ky * 192;
    int kx = r2 / 24;
    int oc = r2 - kx * 24;
    float v = (kx < 7 && oc < 18) ? w_off[(oc * 64 + c) * 49 + ky * 7 + kx] : 0.f;
    g_wtB[idx] = __uint_as_float(f2tf32(v));
}

// ---------------------------------------------------------------------------
// Kernel 1: offset conv via TF32 mma (unchanged).
// ---------------------------------------------------------------------------
#define OCW 272
#define WT_F 3808
__global__ __launch_bounds__(256) void offset_mma_kernel(const float* __restrict__ x)
{
    __shared__ float sm[6496];

    const int tid = threadIdx.x;
    const int wid = tid >> 5;
    const int l   = tid & 31;
    const int lq  = l >> 2;
    const int lr  = l & 3;
    const int bx  = blockIdx.x;
    const int b   = bx >> 7;
    const int ho  = bx & 127;
    const int y0  = 2 * ho - 3;
    const uint32_t su = smem_u32(sm);

    const float* xb = x + ((size_t)b << 22);

    for (int i = tid; i < 2 * 7 * 16; i += 256) {
        const int buf = i >= 112;
        const int r   = i - buf * 112;
        const int row = r >> 4;
        const int k   = r & 15;
        const int col = (k < 4) ? k : 256 + k;
        sm[buf * 1904 + row * OCW + col] = 0.f;
    }

    {
        for (int i = tid; i < 448; i += 256) {
            const int r = i >> 6, q = i & 63;
            const int y = y0 + r;
            const int yc = min(max(y, 0), 255);
            const uint32_t sz = (y >= 0 && y < 256) ? 16u : 0u;
            CPA16(su + (uint32_t)(r * OCW * 4 + 16 + q * 16), xb + yc * 256 + q * 4, sz);
        }
        for (int i = tid; i < 336; i += 256)
            CPA16(su + (uint32_t)(WT_F * 4 + i * 16), g_wtB + i * 4, 16u);
        CPA_COMMIT();
    }

    float acc[3][4];
#pragma unroll
    for (int n = 0; n < 3; n++)
#pragma unroll
        for (int q = 0; q < 4; q++) acc[n][q] = 0.f;

    const int px2 = 2 * (16 * wid + lq) + 1;

    for (int c = 0; c < 64; c++) {
        CPA_WAIT0();
        __syncthreads();

        if (c + 1 < 64) {
            const int nb = (c + 1) & 1;
            const float* xc = xb + ((size_t)(c + 1) << 16);
            for (int i = tid; i < 448; i += 256) {
                const int r = i >> 6, q = i & 63;
                const int y = y0 + r;
                const int yc = min(max(y, 0), 255);
                const uint32_t sz = (y >= 0 && y < 256) ? 16u : 0u;
                CPA16(su + (uint32_t)(nb * 1904 * 4 + r * OCW * 4 + 16 + q * 16),
                      xc + yc * 256 + q * 4, sz);
            }
            const float* wsrc = g_wtB + (size_t)(c + 1) * 1344;
            for (int i = tid; i < 336; i += 256)
                CPA16(su + (uint32_t)(WT_F * 4 + nb * 5376 + i * 16),
                      wsrc + i * 4, 16u);
            CPA_COMMIT();
        }

        const float* W  = sm + (c & 1) * 1904;
        const float* Bw = sm + WT_F + (c & 1) * 1344;
#pragma unroll
        for (int ky = 0; ky < 7; ky++) {
            const float* wr = W + ky * OCW;
            const uint32_t a0 = f2tf32(wr[px2 + lr]);
            const uint32_t a1 = f2tf32(wr[px2 + 16 + lr]);
            const uint32_t a2 = f2tf32(wr[px2 + 4 + lr]);
            const uint32_t a3 = f2tf32(wr[px2 + 20 + lr]);
            const float* bb = Bw + ky * 192;
#pragma unroll
            for (int nt = 0; nt < 3; nt++) {
                const uint32_t b0 = __float_as_uint(bb[lr * 24 + nt * 8 + lq]);
                const uint32_t b1 = __float_as_uint(bb[(lr + 4) * 24 + nt * 8 + lq]);
                mma_tf32(acc[nt], a0, a1, a2, a3, b0, b1);
            }
        }
    }

    const int px = 16 * wid + lq;
#pragma unroll
    for (int nt = 0; nt < 3; nt++) {
        const int oc0 = nt * 8 + 2 * lr;
        if (oc0 < 18) {
            float* op = g_offp + (((size_t)(b * 18 + oc0)) << 14) + ho * 128;
            op[px]     = acc[nt][0];
            op[px + 8] = acc[nt][2];
        }
        if (oc0 + 1 < 18) {
            float* op = g_offp + (((size_t)(b * 18 + oc0 + 1)) << 14) + ho * 128;
            op[px]     = acc[nt][1];
            op[px + 8] = acc[nt][3];
        }
    }
}

// ---------------------------------------------------------------------------
// Kernel 2: fused deformable gather + TF32 mma GEMM + bias + GN partials.
// R13: NO smem windows — gather reads x directly from global (4 LDG.32 per
// item; corner pairs adjacent => coalesced-ish, L1-resident across taps).
// x-boundary select folded into per-item weights (A,B), row offsets packed.
// Channels within an 8-group write disjoint Bs rows => syncs drop from
// 2/channel to 2/group (128 -> 16).
// smem (bytes): [0,39168) Bs 72x136 fl, [39168,78080) As 128x76 fl.
// ---------------------------------------------------------------------------
#define BS_OFF 0
#define AS_OFF 39168
#define FUSED_SMEM 78080

__global__ __launch_bounds__(256, 2) void fused_kernel(
    const float* __restrict__ x,
    const float* __restrict__ b_off,
    const float* __restrict__ bias,
    float* __restrict__ out)
{
    extern __shared__ char smem[];
    __shared__ float eps[64], epq[64];
    const uint32_t su = smem_u32(smem);
    const int tid = threadIdx.x;
    const int wid = tid >> 5;
    const int l   = tid & 31;
    const int bx  = blockIdx.x;
    const int b   = bx >> 7;
    const int ho  = bx & 127;

    uint32_t* Bs = (uint32_t*)(smem + BS_OFF);
    const float* xb = x + ((size_t)b << 22);

    // ---- prefetch A(group 0) ----
    for (int i = tid; i < 2432; i += 256)
        CPA16(su + AS_OFF + (uint32_t)(i * 16), g_wtA + i * 4, 16u);
    CPA_COMMIT();

    // ---- gather metadata -> REGISTERS (<=5 items per thread) ----
    // Per item: mwr = (wy0, wy1, A, B); mir = packed (off0 | off1<<16).
    // A,B fold the x-boundary corner-select into weights:
    //   val_row = A*x[row][base] + B*x[row][base+1], base = clamp(x0,0,254).
    const int wo    = tid & 127;
    const int tidhi = tid >> 7;
    float4   mwr[5];
    uint32_t mir[5];
#pragma unroll
    for (int k = 0; k < 5; k++) {
        const int tap = tidhi + 2 * k;
        if (tap > 8) break;           // only k==4 & tidhi==1
        const int ky = tap / 3;
        const int kx = tap - ky * 3;
        const int hw = ho * 128 + wo;

        const float dy = b_off[tap * 2 + 0]
            + g_offp[(((size_t)(b * 18 + tap * 2 + 0)) << 14) + hw];
        const float dx = b_off[tap * 2 + 1]
            + g_offp[(((size_t)(b * 18 + tap * 2 + 1)) << 14) + hw];

        const float yf = (float)(2 * ho - 1 + ky) + dy;
        const float xf = (float)(2 * wo - 1 + kx) + dx;
        const float y0f = floorf(yf), x0f = floorf(xf);
        const int y0 = (int)y0f, x0 = (int)x0f;
        const float wy1 = yf - y0f, wy0 = 1.f - wy1;
        const float wx1 = xf - x0f, wx0 = 1.f - wx1;

        const float wz = ((x0 >= 0) & (x0 < 256))         ? wx0 : 0.f;
        const float ww = ((x0 + 1 >= 0) & (x0 + 1 < 256)) ? wx1 : 0.f;

        float4 w;
        w.x = ((y0 >= 0) & (y0 < 256))         ? wy0 : 0.f;
        w.y = ((y0 + 1 >= 0) & (y0 + 1 < 256)) ? wy1 : 0.f;
        w.z = (x0 <= 254 ? wz : 0.f) + (x0 < 0 ? ww : 0.f);   // A
        w.w = (x0 >  254 ? wz : 0.f) + (x0 >= 0 ? ww : 0.f);  // B
        mwr[k] = w;

        const int base = min(max(x0, 0), 254);
        const int y0c  = min(max(y0, 0), 255);
        const int y1c  = min(max(y0 + 1, 0), 255);
        mir[k] = (uint32_t)(y0c * 256 + base) | ((uint32_t)(y1c * 256 + base) << 16);
    }

    // ---- accumulators ----
    float acc[4][4][4];
#pragma unroll
    for (int i = 0; i < 4; i++)
#pragma unroll
        for (int j = 0; j < 4; j++)
#pragma unroll
            for (int q = 0; q < 4; q++) acc[i][j][q] = 0.f;

    const int mg = wid & 1;
    const int ng = wid >> 1;
    const int lq = l >> 2;
    const int lr = l & 3;
    const uint32_t aBase = su + AS_OFF
        + (uint32_t)(((mg * 64 + (l & 15)) * 76 + ((l >> 4) << 2)) * 4);
    const int bBase = lr * 136 + ng * 32 + lq;

    // ---- mainloop: 8 groups of 8 channels ----
    for (int g = 0; g < 8; g++) {
        // gather 8 channels straight from global into Bs (disjoint rows per c)
#pragma unroll 1
        for (int c8 = 0; c8 < 8; c8++) {
            const int c = g * 8 + c8;
            const float* xc = xb + ((size_t)c << 16);
            const int rbase = (9 * c8 + tidhi) * 136 + wo;
#pragma unroll
            for (int k = 0; k < 5; k++) {
                if (k == 4 && tidhi) break;
                const float4 w = mwr[k];
                const uint32_t pp = mir[k];
                const int o0 = pp & 0xFFFF;
                const int o1 = pp >> 16;
                const float f00 = __ldg(xc + o0);
                const float f01 = __ldg(xc + o0 + 1);
                const float f10 = __ldg(xc + o1);
                const float f11 = __ldg(xc + o1 + 1);
                const float top = w.z * f00 + w.w * f01;
                const float bot = w.z * f10 + w.w * f11;
                Bs[rbase + k * 272] = f2tf32(w.x * top + w.y * bot);
            }
        }

        CPA_WAIT0();          // As(g) arrived
        __syncthreads();      // Bs tile complete + As visible

#pragma unroll
        for (int ks = 0; ks < 9; ks++) {
            const int k0 = ks * 8;
            uint32_t a0[4], a1[4], a2[4], a3[4], b0[4], b1[4];
#pragma unroll
            for (int mt = 0; mt < 4; mt++)
                ldsm_x4(a0[mt], a1[mt], a2[mt], a3[mt],
                        aBase + (uint32_t)(mt * 4864 + k0 * 4));
#pragma unroll
            for (int nt = 0; nt < 4; nt++) {
                b0[nt] = Bs[bBase + k0 * 136 + nt * 8];
                b1[nt] = Bs[bBase + k0 * 136 + 544 + nt * 8];
            }
#pragma unroll
            for (int mt = 0; mt < 4; mt++)
#pragma unroll
                for (int nt = 0; nt < 4; nt++)
                    mma_tf32(acc[mt][nt], a0[mt], a1[mt], a2[mt], a3[mt],
                             b0[nt], b1[nt]);
        }

        __syncthreads();      // mma done: Bs reusable, As rewritable

        if (g + 1 < 8) {      // prefetch A(g+1); overlaps next group's gather
            const float* asrc = g_wtA + (size_t)(g + 1) * 9728;
            for (int i = tid; i < 2432; i += 256)
                CPA16(su + AS_OFF + (uint32_t)(i * 16), asrc + i * 4, 16u);
            CPA_COMMIT();
        }
    }

    // ---- epilogue: bias, store, GN partials ----
#pragma unroll
    for (int mt = 0; mt < 4; mt++) {
        const int m0 = mg * 64 + mt * 16 + lq;
        const float bv0 = bias[m0];
        const float bv1 = bias[m0 + 8];
        float s0 = 0.f, q0 = 0.f, s1 = 0.f, q1 = 0.f;
#pragma unroll
        for (int nt = 0; nt < 4; nt++) {
            const int col = ng * 32 + nt * 8 + 2 * lr;
            float v0 = acc[mt][nt][0] + bv0;
            float v1 = acc[mt][nt][1] + bv0;
            float v2 = acc[mt][nt][2] + bv1;
            float v3 = acc[mt][nt][3] + bv1;
            s0 += v0 + v1; q0 += v0 * v0 + v1 * v1;
            s1 += v2 + v3; q1 += v2 * v2 + v3 * v3;
            *(float2*)(out + (((size_t)(b * 128 + m0)) << 14) + ho * 128 + col)
                = make_float2(v0, v1);
            *(float2*)(out + (((size_t)(b * 128 + m0 + 8)) << 14) + ho * 128 + col)
                = make_float2(v2, v3);
        }
#pragma unroll
        for (int off = 16; off > 0; off >>= 1) {
            s0 += __shfl_xor_sync(0xffffffffu, s0, off);
            q0 += __shfl_xor_sync(0xffffffffu, q0, off);
            s1 += __shfl_xor_sync(0xffffffffu, s1, off);
            q1 += __shfl_xor_sync(0xffffffffu, q1, off);
        }
        if (l == 0) {
            eps[wid * 8 + mt * 2 + 0] = s0;
            epq[wid * 8 + mt * 2 + 0] = q0;
            eps[wid * 8 + mt * 2 + 1] = s1;
            epq[wid * 8 + mt * 2 + 1] = q1;
        }
    }
    __syncthreads();
    if (tid < 16) {
        const int g = tid;
        const int gm = g >> 3;
        const int slot = g & 7;
        float S = 0.f, Q = 0.f;
#pragma unroll
        for (int j = 0; j < 4; j++) {
            const int w = gm + j * 2;
            S += eps[w * 8 + slot];
            Q += epq[w * 8 + slot];
        }
        g_psum[bx * 16 + g] = S;
        g_psq [bx * 16 + g] = Q;
    }
}

// ---------------------------------------------------------------------------
// Kernel 3: GroupNorm finalize.
// ---------------------------------------------------------------------------
__global__ __launch_bounds__(256) void gn_final_kernel(
    float* __restrict__ out,
    const float* __restrict__ gamma,
    const float* __restrict__ beta)
{
    __shared__ float rs[128], rq[128];
    const int tid  = threadIdx.x;
    const int g64  = blockIdx.x >> 3;
    const int part = blockIdx.x & 7;
    const int b    = g64 >> 4;
    const int g    = g64 & 15;

    if (tid < 128) {
        rs[tid] = g_psum[(b * 128 + tid) * 16 + g];
        rq[tid] = g_psq [(b * 128 + tid) * 16 + g];
    }
    __syncthreads();
    for (int s = 64; s > 0; s >>= 1) {
        if (tid < s) { rs[tid] += rs[tid + s]; rq[tid] += rq[tid + s]; }
        __syncthreads();
    }
    const float mu   = rs[0] * (1.f / 131072.f);
    const float var  = rq[0] * (1.f / 131072.f) - mu * mu;
    const float rsig = rsqrtf(var + 1e-5f);

    const int ch = g * 8 + part;
    const float ga = gamma[ch] * rsig;
    const float be = beta[ch] - mu * ga;

    float4* p = (float4*)(out + (((size_t)(b * 128 + ch)) << 14));
    for (int i = tid; i < 4096; i += 256) {
        float4 v = p[i];
        v.x = v.x * ga + be; v.y = v.y * ga + be;
        v.z = v.z * ga + be; v.w = v.w * ga + be;
        p[i] = v;
    }
}

// ---------------------------------------------------------------------------
extern "C" void kernel_launch(void* const* d_in, const int* in_sizes, int n_in,
                              void* d_out, int out_size)
{
    const float* x      = (const float*)d_in[0];
    const float* w_off  = (const float*)d_in[1];
    const float* b_off  = (const float*)d_in[2];
    const float* weight = (const float*)d_in[3];
    const float* bias   = (const float*)d_in[4];
    const float* gamma  = (const float*)d_in[5];
    const float* beta   = (const float*)d_in[6];
    float* out = (float*)d_out;

    cudaFuncSetAttribute(fused_kernel,
                         cudaFuncAttributeMaxDynamicSharedMemorySize, FUSED_SMEM);

    prep_wt_kernel<<<304, 256>>>(weight);
    prep_wtB_kernel<<<336, 256>>>(w_off);
    offset_mma_kernel<<<512, 256>>>(x);
    fused_kernel<<<512, 256, FUSED_SMEM>>>(x, b_off, bias, out);
    gn_final_kernel<<<512, 256>>>(out, gamma, beta);
}

// round 14
// speedup vs baseline: 1.1370x; 1.1370x over previous
#include <cuda_runtime.h>
#include <cuda_bf16.h>
#include <cstdint>

// Dims: B=4, C_IN=64, C_OUT=128, H=W=256, HO=WO=128, K=3 (9 taps), K_OFF=7

// ---------------- scratch ----------------
#define OFFP_HALF (4 * 18 * 128 * 128)
__device__ float g_offp[2 * OFFP_HALF];            // offset conv output, 2 ch-half partials
__device__ float g_wtA[8 * 128 * 76];              // deform A: [group8ch][m][76]
__device__ float g_wtB[64 * 7 * 8 * 24];           // offset weights: [ch][ky][kx8][oc24]
__device__ float g_psum[512 * 16];
__device__ float g_psq[512 * 16];

// ---------------- helpers ----------------
__device__ __forceinline__ uint32_t smem_u32(const void* p) {
    uint32_t a;
    asm("{ .reg .u64 t; cvta.to.shared.u64 t, %1; cvt.u32.u64 %0, t; }" : "=r"(a) : "l"(p));
    return a;
}
__device__ __forceinline__ uint32_t f2tf32(float f) {
    uint32_t u;
    asm("cvt.rna.tf32.f32 %0, %1;" : "=r"(u) : "f"(f));
    return u;
}
__device__ __forceinline__ void mma_tf32(float* d, uint32_t a0, uint32_t a1,
                                         uint32_t a2, uint32_t a3,
                                         uint32_t b0, uint32_t b1) {
    asm volatile(
        "mma.sync.aligned.m16n8k8.row.col.f32.tf32.tf32.f32 "
        "{%0,%1,%2,%3}, {%4,%5,%6,%7}, {%8,%9}, {%0,%1,%2,%3};"
        : "+f"(d[0]), "+f"(d[1]), "+f"(d[2]), "+f"(d[3])
        : "r"(a0), "r"(a1), "r"(a2), "r"(a3), "r"(b0), "r"(b1));
}
__device__ __forceinline__ void ldsm_x4(uint32_t& r0, uint32_t& r1, uint32_t& r2,
                                        uint32_t& r3, uint32_t addr) {
    asm volatile("ldmatrix.sync.aligned.m8n8.x4.shared.b16 {%0,%1,%2,%3}, [%4];"
                 : "=r"(r0), "=r"(r1), "=r"(r2), "=r"(r3) : "r"(addr));
}

#define CPA16(dst, src, sz) \
    asm volatile("cp.async.cg.shared.global [%0], [%1], 16, %2;" :: "r"(dst), "l"(src), "r"(sz))
#define CPA_COMMIT() asm volatile("cp.async.commit_group;" ::: "memory")
#define CPA_WAIT0()  asm volatile("cp.async.wait_group 0;" ::: "memory")

// ---------------------------------------------------------------------------
// Kernel 0a: deform-conv A prep
// ---------------------------------------------------------------------------
__global__ __launch_bounds__(256) void prep_wt_kernel(const float* __restrict__ weight)
{
    int idx = blockIdx.x * 256 + threadIdx.x;       // 77824 total
    if (idx >= 8 * 128 * 76) return;
    int g   = idx / 9728;
    int rem = idx - g * 9728;
    int m   = rem / 76;
    int kk  = rem - m * 76;
    float v = (kk < 72) ? weight[m * 576 + g * 72 + kk] : 0.f;
    g_wtA[idx] = __uint_as_float(f2tf32(v));
}

// ---------------------------------------------------------------------------
// Kernel 0b: offset-conv weight prep: g_wtB[c][ky][kx(8)][oc(24)]
// ---------------------------------------------------------------------------
__global__ __launch_bounds__(256) void prep_wtB_kernel(const float* __restrict__ w_off)
{
    int idx = blockIdx.x * 256 + threadIdx.x;
    if (idx >= 64 * 1344) return;
    int c  = idx / 1344;
    int r  = idx - c * 1344;
    int ky = r / 192;
    int r2 = r - ky * 192;
    int kx = r2 / 24;
    int oc = r2 - kx * 24;
    float v = (kx < 7 && oc < 18) ? w_off[(oc * 64 + c) * 49 + ky * 7 + kx] : 0.f;
    g_wtB[idx] = __uint_as_float(f2tf32(v));
}

// ---------------------------------------------------------------------------
// Kernel 1: offset conv via TF32 mma, SPLIT-K x2 (R14).
// Grid 1024: bx = half*512 + (b*128 + ho). Each block does 32 channels into
// g_offp[half] partials. Halves the per-block serial chain and doubles
// concurrent blocks (latency-bound hypothesis).
// ---------------------------------------------------------------------------
#define OCW 272
#define WT_F 3808
__global__ __launch_bounds__(256) void offset_mma_kernel(const float* __restrict__ x)
{
    __shared__ float sm[6496];

    const int tid = threadIdx.x;
    const int wid = tid >> 5;
    const int l   = tid & 31;
    const int lq  = l >> 2;
    const int lr  = l & 3;
    const int bx   = blockIdx.x;
    const int half = bx >> 9;
    const int row  = bx & 511;
    const int b   = row >> 7;
    const int ho  = row & 127;
    const int y0  = 2 * ho - 3;
    const uint32_t su = smem_u32(sm);

    const float* xb = x + ((size_t)b << 22);
    const int c0 = half * 32;

    for (int i = tid; i < 2 * 7 * 16; i += 256) {
        const int buf = i >= 112;
        const int r   = i - buf * 112;
        const int rw  = r >> 4;
        const int k   = r & 15;
        const int col = (k < 4) ? k : 256 + k;
        sm[buf * 1904 + rw * OCW + col] = 0.f;
    }

    {
        const float* xc = xb + ((size_t)c0 << 16);
        for (int i = tid; i < 448; i += 256) {
            const int r = i >> 6, q = i & 63;
            const int y = y0 + r;
            const int yc = min(max(y, 0), 255);
            const uint32_t sz = (y >= 0 && y < 256) ? 16u : 0u;
            CPA16(su + (uint32_t)(r * OCW * 4 + 16 + q * 16), xc + yc * 256 + q * 4, sz);
        }
        const float* wsrc = g_wtB + (size_t)c0 * 1344;
        for (int i = tid; i < 336; i += 256)
            CPA16(su + (uint32_t)(WT_F * 4 + i * 16), wsrc + i * 4, 16u);
        CPA_COMMIT();
    }

    float acc[3][4];
#pragma unroll
    for (int n = 0; n < 3; n++)
#pragma unroll
        for (int q = 0; q < 4; q++) acc[n][q] = 0.f;

    const int px2 = 2 * (16 * wid + lq) + 1;

    for (int c = 0; c < 32; c++) {
        CPA_WAIT0();
        __syncthreads();

        if (c + 1 < 32) {
            const int nb = (c + 1) & 1;
            const float* xc = xb + ((size_t)(c0 + c + 1) << 16);
            for (int i = tid; i < 448; i += 256) {
                const int r = i >> 6, q = i & 63;
                const int y = y0 + r;
                const int yc = min(max(y, 0), 255);
                const uint32_t sz = (y >= 0 && y < 256) ? 16u : 0u;
                CPA16(su + (uint32_t)(nb * 1904 * 4 + r * OCW * 4 + 16 + q * 16),
                      xc + yc * 256 + q * 4, sz);
            }
            const float* wsrc = g_wtB + (size_t)(c0 + c + 1) * 1344;
            for (int i = tid; i < 336; i += 256)
                CPA16(su + (uint32_t)(WT_F * 4 + nb * 5376 + i * 16),
                      wsrc + i * 4, 16u);
            CPA_COMMIT();
        }

        const float* W  = sm + (c & 1) * 1904;
        const float* Bw = sm + WT_F + (c & 1) * 1344;
#pragma unroll
        for (int ky = 0; ky < 7; ky++) {
            const float* wr = W + ky * OCW;
            const uint32_t a0 = f2tf32(wr[px2 + lr]);
            const uint32_t a1 = f2tf32(wr[px2 + 16 + lr]);
            const uint32_t a2 = f2tf32(wr[px2 + 4 + lr]);
            const uint32_t a3 = f2tf32(wr[px2 + 20 + lr]);
            const float* bb = Bw + ky * 192;
#pragma unroll
            for (int nt = 0; nt < 3; nt++) {
                const uint32_t b0 = __float_as_uint(bb[lr * 24 + nt * 8 + lq]);
                const uint32_t b1 = __float_as_uint(bb[(lr + 4) * 24 + nt * 8 + lq]);
                mma_tf32(acc[nt], a0, a1, a2, a3, b0, b1);
            }
        }
    }

    const int px = 16 * wid + lq;
    float* ob = g_offp + (size_t)half * OFFP_HALF;
#pragma unroll
    for (int nt = 0; nt < 3; nt++) {
        const int oc0 = nt * 8 + 2 * lr;
        if (oc0 < 18) {
            float* op = ob + (((size_t)(b * 18 + oc0)) << 14) + ho * 128;
            op[px]     = acc[nt][0];
            op[px + 8] = acc[nt][2];
        }
        if (oc0 + 1 < 18) {
            float* op = ob + (((size_t)(b * 18 + oc0 + 1)) << 14) + ho * 128;
            op[px]     = acc[nt][1];
            op[px + 8] = acc[nt][3];
        }
    }
}

// ---------------------------------------------------------------------------
// Kernel 2: fused deformable gather + TF32 mma GEMM + bias + GN partials.
// (R12 structure verbatim; metadata sums the two offset partials.)
// smem (bytes): [0,24576) 2x window (12x256 fl)
//               [24576,63744) Bs 72x136 fl (k-major, stride 136)
//               [63744,102656) As 128x76 fl
// ---------------------------------------------------------------------------
#define WINB   12288
#define BS_OFF 24576
#define AS_OFF 63744
#define FUSED_SMEM 102656

__global__ __launch_bounds__(256, 2) void fused_kernel(
    const float* __restrict__ x,
    const float* __restrict__ b_off,
    const float* __restrict__ bias,
    float* __restrict__ out)
{
    extern __shared__ char smem[];
    __shared__ float eps[64], epq[64];
    const uint32_t su = smem_u32(smem);
    const int tid = threadIdx.x;
    const int wid = tid >> 5;
    const int l   = tid & 31;
    const int bx  = blockIdx.x;
    const int b   = bx >> 7;
    const int ho  = bx & 127;
    const int yb  = 2 * ho - 5;        // 12-row window: y in [yb, yb+11]

    uint32_t* Bs = (uint32_t*)(smem + BS_OFF);
    const float* xb = x + ((size_t)b << 22);

    // ---- prefetch window(0) + A(group 0) ----
    {
        for (int i = tid; i < 768; i += 256) {
            const int r = i >> 6, q = i & 63;
            const int y = yb + r;
            const int yc = min(max(y, 0), 255);
            const uint32_t sz = (y >= 0 && y < 256) ? 16u : 0u;
            CPA16(su + (i << 4), xb + yc * 256 + q * 4, sz);
        }
        for (int i = tid; i < 2432; i += 256)
            CPA16(su + AS_OFF + (uint32_t)(i * 16), g_wtA + i * 4, 16u);
        CPA_COMMIT();
    }

    // ---- gather metadata -> REGISTERS (<=5 items per thread) ----
    const int wo    = tid & 127;
    const int tidhi = tid >> 7;
    float4 mwr[5];
    int    mir[5];
#pragma unroll
    for (int k = 0; k < 5; k++) {
        const int tap = tidhi + 2 * k;
        if (tap > 8) break;           // only k==4 & tidhi==1
        const int ky = tap / 3;
        const int kx = tap - ky * 3;
        const int hw = ho * 128 + wo;

        const size_t oy = (((size_t)(b * 18 + tap * 2 + 0)) << 14) + hw;
        const size_t ox = (((size_t)(b * 18 + tap * 2 + 1)) << 14) + hw;
        const float dy = b_off[tap * 2 + 0] + g_offp[oy] + g_offp[OFFP_HALF + oy];
        const float dx = b_off[tap * 2 + 1] + g_offp[ox] + g_offp[OFFP_HALF + ox];

        const float yf = (float)(2 * ho - 1 + ky) + dy;
        const float xf = (float)(2 * wo - 1 + kx) + dx;
        const float y0f = floorf(yf), x0f = floorf(xf);
        const int y0 = (int)y0f, x0 = (int)x0f;
        const float wy1 = yf - y0f, wy0 = 1.f - wy1;
        const float wx1 = xf - x0f, wx0 = 1.f - wx1;

        float4 w;
        w.x = ((y0 >= 0) & (y0 < 256))         ? wy0 : 0.f;
        w.y = ((y0 + 1 >= 0) & (y0 + 1 < 256)) ? wy1 : 0.f;
        w.z = ((x0 >= 0) & (x0 < 256))         ? wx0 : 0.f;
        w.w = ((x0 + 1 >= 0) & (x0 + 1 < 256)) ? wx1 : 0.f;
        mwr[k] = w;

        const int wy  = min(max(y0 - yb, 0), 10);
        const int x0c = min(max(x0, 0), 255);
        const int x1c = min(max(x0 + 1, 0), 255);
        mir[k] = (wy * 256 + x0c) | ((x1c - x0c) << 16);
    }

    // ---- accumulators ----
    float acc[4][4][4];
#pragma unroll
    for (int i = 0; i < 4; i++)
#pragma unroll
        for (int j = 0; j < 4; j++)
#pragma unroll
            for (int q = 0; q < 4; q++) acc[i][j][q] = 0.f;

    const int mg = wid & 1;
    const int ng = wid >> 1;
    const int lq = l >> 2;
    const int lr = l & 3;
    const uint32_t aBase = su + AS_OFF
        + (uint32_t)(((mg * 64 + (l & 15)) * 76 + ((l >> 4) << 2)) * 4);
    const int bBase = lr * 136 + ng * 32 + lq;

    // ---- mainloop over 64 channels (8 groups of 8) ----
    for (int c = 0; c < 64; c++) {
        CPA_WAIT0();
        __syncthreads();   // window(c)/A ready; mma(prev group) done block-wide

        if (c + 1 < 64) {
            const float* xc = xb + ((size_t)(c + 1) << 16);
            const uint32_t wdst = su + (uint32_t)(((c + 1) & 1) * WINB);
            for (int i = tid; i < 768; i += 256) {
                const int r = i >> 6, q = i & 63;
                const int y = yb + r;
                const int yc = min(max(y, 0), 255);
                const uint32_t sz = (y >= 0 && y < 256) ? 16u : 0u;
                CPA16(wdst + (i << 4), xc + yc * 256 + q * 4, sz);
            }
            if ((c & 7) == 0 && c > 0) {      // load A(group c>>3); prev done
                const float* asrc = g_wtA + (size_t)(c >> 3) * 9728;
                for (int i = tid; i < 2432; i += 256)
                    CPA16(su + AS_OFF + (uint32_t)(i * 16), asrc + i * 4, 16u);
            }
            CPA_COMMIT();
        }

        // gather channel c into Bs rows 9*(c&7)+tap (k-major; metadata in regs)
        const float* win = (const float*)(smem + (c & 1) * WINB);
        const int rbase = (9 * (c & 7) + tidhi) * 136 + wo;
#pragma unroll
        for (int k = 0; k < 5; k++) {
            if (k == 4 && tidhi) break;
            const float4 w = mwr[k];
            const int mm = mir[k];
            const int i00 = mm & 0xFFFF;
            const int i01 = i00 + (mm >> 16);
            const float top = w.z * win[i00]       + w.w * win[i01];
            const float bot = w.z * win[i00 + 256] + w.w * win[i01 + 256];
            Bs[rbase + k * 272] = f2tf32(w.x * top + w.y * bot);   // +2 rows per k
        }

        if ((c & 7) == 7) {
            __syncthreads();   // group B tile complete
#pragma unroll
            for (int ks = 0; ks < 9; ks++) {
                const int k0 = ks * 8;
                uint32_t a0[4], a1[4], a2[4], a3[4], b0[4], b1[4];
#pragma unroll
                for (int mt = 0; mt < 4; mt++)
                    ldsm_x4(a0[mt], a1[mt], a2[mt], a3[mt],
                            aBase + (uint32_t)(mt * 4864 + k0 * 4));
#pragma unroll
                for (int nt = 0; nt < 4; nt++) {
                    b0[nt] = Bs[bBase + k0 * 136 + nt * 8];
                    b1[nt] = Bs[bBase + k0 * 136 + 544 + nt * 8];
                }
#pragma unroll
                for (int mt = 0; mt < 4; mt++)
#pragma unroll
                    for (int nt = 0; nt < 4; nt++)
                        mma_tf32(acc[mt][nt], a0[mt], a1[mt], a2[mt], a3[mt],
                                 b0[nt], b1[nt]);
            }
        }
    }

    // ---- epilogue: bias, store, GN partials ----
#pragma unroll
    for (int mt = 0; mt < 4; mt++) {
        const int m0 = mg * 64 + mt * 16 + lq;
        const float bv0 = bias[m0];
        const float bv1 = bias[m0 + 8];
        float s0 = 0.f, q0 = 0.f, s1 = 0.f, q1 = 0.f;
#pragma unroll
        for (int nt = 0; nt < 4; nt++) {
            const int col = ng * 32 + nt * 8 + 2 * lr;
            float v0 = acc[mt][nt][0] + bv0;
            float v1 = acc[mt][nt][1] + bv0;
            float v2 = acc[mt][nt][2] + bv1;
            float v3 = acc[mt][nt][3] + bv1;
            s0 += v0 + v1; q0 += v0 * v0 + v1 * v1;
            s1 += v2 + v3; q1 += v2 * v2 + v3 * v3;
            *(float2*)(out + (((size_t)(b * 128 + m0)) << 14) + ho * 128 + col)
                = make_float2(v0, v1);
            *(float2*)(out + (((size_t)(b * 128 + m0 + 8)) << 14) + ho * 128 + col)
                = make_float2(v2, v3);
        }
#pragma unroll
        for (int off = 16; off > 0; off >>= 1) {
            s0 += __shfl_xor_sync(0xffffffffu, s0, off);
            q0 += __shfl_xor_sync(0xffffffffu, q0, off);
            s1 += __shfl_xor_sync(0xffffffffu, s1, off);
            q1 += __shfl_xor_sync(0xffffffffu, q1, off);
        }
        if (l == 0) {
            eps[wid * 8 + mt * 2 + 0] = s0;
            epq[wid * 8 + mt * 2 + 0] = q0;
            eps[wid * 8 + mt * 2 + 1] = s1;
            epq[wid * 8 + mt * 2 + 1] = q1;
        }
    }
    __syncthreads();
    if (tid < 16) {
        const int g = tid;
        const int gm = g >> 3;
        const int slot = g & 7;
        float S = 0.f, Q = 0.f;
#pragma unroll
        for (int j = 0; j < 4; j++) {
            const int w = gm + j * 2;
            S += eps[w * 8 + slot];
            Q += epq[w * 8 + slot];
        }
        g_psum[bx * 16 + g] = S;
        g_psq [bx * 16 + g] = Q;
    }
}

// ---------------------------------------------------------------------------
// Kernel 3: GroupNorm finalize.
// ---------------------------------------------------------------------------
__global__ __launch_bounds__(256) void gn_final_kernel(
    float* __restrict__ out,
    const float* __restrict__ gamma,
    const float* __restrict__ beta)
{
    __shared__ float rs[128], rq[128];
    const int tid  = threadIdx.x;
    const int g64  = blockIdx.x >> 3;
    const int part = blockIdx.x & 7;
    const int b    = g64 >> 4;
    const int g    = g64 & 15;

    if (tid < 128) {
        rs[tid] = g_psum[(b * 128 + tid) * 16 + g];
        rq[tid] = g_psq [(b * 128 + tid) * 16 + g];
    }
    __syncthreads();
    for (int s = 64; s > 0; s >>= 1) {
        if (tid < s) { rs[tid] += rs[tid + s]; rq[tid] += rq[tid + s]; }
        __syncthreads();
    }
    const float mu   = rs[0] * (1.f / 131072.f);
    const float var  = rq[0] * (1.f / 131072.f) - mu * mu;
    const float rsig = rsqrtf(var + 1e-5f);

    const int ch = g * 8 + part;
    const float ga = gamma[ch] * rsig;
    const float be = beta[ch] - mu * ga;

    float4* p = (float4*)(out + (((size_t)(b * 128 + ch)) << 14));
    for (int i = tid; i < 4096; i += 256) {
        float4 v = p[i];
        v.x = v.x * ga + be; v.y = v.y * ga + be;
        v.z = v.z * ga + be; v.w = v.w * ga + be;
        p[i] = v;
    }
}

// ---------------------------------------------------------------------------
extern "C" void kernel_launch(void* const* d_in, const int* in_sizes, int n_in,
                              void* d_out, int out_size)
{
    const float* x      = (const float*)d_in[0];
    const float* w_off  = (const float*)d_in[1];
    const float* b_off  = (const float*)d_in[2];
    const float* weight = (const float*)d_in[3];
    const float* bias   = (const float*)d_in[4];
    const float* gamma  = (const float*)d_in[5];
    const float* beta   = (const float*)d_in[6];
    float* out = (float*)d_out;

    cudaFuncSetAttribute(fused_kernel,
                         cudaFuncAttributeMaxDynamicSharedMemorySize, FUSED_SMEM);

    prep_wt_kernel<<<304, 256>>>(weight);
    prep_wtB_kernel<<<336, 256>>>(w_off);
    offset_mma_kernel<<<1024, 256>>>(x);
    fused_kernel<<<512, 256, FUSED_SMEM>>>(x, b_off, bias, out);
    gn_final_kernel<<<512, 256>>>(out, gamma, beta);
}